// round 10
// baseline (speedup 1.0000x reference)
#include <cuda_runtime.h>
#include <math.h>
#include <stdint.h>

// ----- problem constants -----
#define BB 64      // batch
#define TE 128     // encoder timesteps
#define TD 64      // decoder timesteps
#define DE 512     // embedding dim
#define DH 1024    // hidden dim (enc & dec)
#define H3 3072    // 3 * DH
#define VV 32000   // vocab
#define DIN (DE + DH) // decoder input dim = 1536

// ----- scratch (static device globals; no allocation allowed) -----
__device__ float g_xe[(size_t)TE * BB * DE];
__device__ float g_gi_enc[(size_t)TE * BB * H3];
__device__ float g_wdec[(size_t)TD * BB * DE];
__device__ float g_gi_dec[(size_t)TD * BB * H3];
__device__ float g_gi_ctx[(size_t)BB * H3];
__device__ float g_hA[BB * DH];
__device__ float g_hB[BB * DH];
__device__ float g_states[(size_t)BB * TD * DH];  // (B, T_dec, DH) row-major

// ===================== small PTX helpers =====================

__device__ __forceinline__ void cp16(void* s, const void* g) {
    uint32_t sa = (uint32_t)__cvta_generic_to_shared(s);
    asm volatile("cp.async.cg.shared.global [%0], [%1], 16;\n" :: "r"(sa), "l"(g));
}
__device__ __forceinline__ void cp_commit() {
    asm volatile("cp.async.commit_group;\n");
}
template<int N> __device__ __forceinline__ void cp_wait() {
    asm volatile("cp.async.wait_group %0;\n" :: "n"(N));
}
__device__ __forceinline__ uint32_t f2tf(float x) {
    uint32_t r; asm("cvt.rna.tf32.f32 %0, %1;" : "=r"(r) : "f"(x)); return r;
}
__device__ __forceinline__ void mma_tf32(float* d, const uint32_t* a, const uint32_t* b) {
    asm volatile(
        "mma.sync.aligned.m16n8k8.row.col.f32.tf32.tf32.f32 "
        "{%0,%1,%2,%3}, {%4,%5,%6,%7}, {%8,%9}, {%0,%1,%2,%3};\n"
        : "+f"(d[0]), "+f"(d[1]), "+f"(d[2]), "+f"(d[3])
        : "r"(a[0]), "r"(a[1]), "r"(a[2]), "r"(a[3]), "r"(b[0]), "r"(b[1]));
}

// Blackwell packed fp32x2 FMA (FFMA2): 2 exact fp32 FMAs per instruction.
__device__ __forceinline__ void fma2(unsigned long long& d,
                                     unsigned long long a, unsigned long long b) {
    asm("fma.rn.f32x2 %0, %1, %2, %0;" : "+l"(d) : "l"(a), "l"(b));
}
__device__ __forceinline__ unsigned long long pack_dup(float x) {
    unsigned long long r;
    asm("mov.b64 %0, {%1, %1};" : "=l"(r) : "f"(x));
    return r;
}
__device__ __forceinline__ float2 unpack2(unsigned long long v) {
    float2 r;
    asm("mov.b64 {%0, %1}, %2;" : "=f"(r.x), "=f"(r.y) : "l"(v));
    return r;
}

// ===================== gather kernels =====================

__global__ void gather_enc(const int* __restrict__ x, const float* __restrict__ emb,
                           float* __restrict__ out)
{
    int r = blockIdx.x;
    int t = r >> 6;
    int b = r & 63;
    int tok = x[b * TE + t];
    const float4* s = (const float4*)(emb + (size_t)tok * DE);
    float4* d = (float4*)(out + (size_t)r * DE);
    d[threadIdx.x] = s[threadIdx.x];
}

__global__ void gather_dec(const int* __restrict__ labels, const int* __restrict__ bos,
                           const float* __restrict__ emb, float* __restrict__ out)
{
    int r = blockIdx.x;
    int t = r >> 6;
    int b = r & 63;
    int tok = (t == 0) ? bos[0] : labels[b * TD + t - 1];
    const float4* s = (const float4*)(emb + (size_t)tok * DE);
    float4* d = (float4*)(out + (size_t)r * DE);
    d[threadIdx.x] = s[threadIdx.x];
}

__global__ void set_h(float* __restrict__ dst, const float* __restrict__ src)
{
    int i = blockIdx.x * 1024 + threadIdx.x;
    dst[i] = src ? src[i & (DH - 1)] : 0.0f;
}

// ===================== fp32 SGEMM-NT with FFMA2 (gi / ctx GEMMs: exact fp32) ==========
// C[M,N] = A[M,K](row, lda) * B[N,K](row, ldb)^T + bias[N]
// 128x128x16 tile, 256 threads, 8x8 microtile; inner product via f32x2 packed FMA
// pairing adjacent output columns (B fragments are contiguous -> free pairing).

__global__ __launch_bounds__(256) void sgemm_nt(
    const float* __restrict__ A, const float* __restrict__ Bm,
    const float* __restrict__ bias, float* __restrict__ C,
    int M, int N, int K, int lda, int ldb)
{
    __shared__ __align__(16) float As[16][132];
    __shared__ __align__(16) float Bs[16][132];

    const int t  = threadIdx.x;
    const int tx = t & 15;
    const int ty = t >> 4;
    const int row0 = blockIdx.y * 128;
    const int col0 = blockIdx.x * 128;

    unsigned long long acc2[8][4];
#pragma unroll
    for (int i = 0; i < 8; i++)
#pragma unroll
        for (int j = 0; j < 4; j++) acc2[i][j] = 0ull;

    for (int k0 = 0; k0 < K; k0 += 16) {
#pragma unroll
        for (int r = 0; r < 2; r++) {
            int id = t + 256 * r;
            int ar = id >> 2;
            int kq = id & 3;
            float4 v = make_float4(0.f, 0.f, 0.f, 0.f);
            int gr = row0 + ar;
            if (gr < M) v = *(const float4*)(A + (size_t)gr * lda + k0 + kq * 4);
            As[kq * 4 + 0][ar] = v.x;
            As[kq * 4 + 1][ar] = v.y;
            As[kq * 4 + 2][ar] = v.z;
            As[kq * 4 + 3][ar] = v.w;
            float4 wv = *(const float4*)(Bm + (size_t)(col0 + ar) * ldb + k0 + kq * 4);
            Bs[kq * 4 + 0][ar] = wv.x;
            Bs[kq * 4 + 1][ar] = wv.y;
            Bs[kq * 4 + 2][ar] = wv.z;
            Bs[kq * 4 + 3][ar] = wv.w;
        }
        __syncthreads();

#pragma unroll
        for (int k = 0; k < 16; k++) {
            float4 a0 = *(const float4*)&As[k][ty * 4];
            float4 a1 = *(const float4*)&As[k][ty * 4 + 64];
            ulonglong2 b0 = *(const ulonglong2*)&Bs[k][tx * 4];
            ulonglong2 b1 = *(const ulonglong2*)&Bs[k][tx * 4 + 64];
            float av[8] = {a0.x, a0.y, a0.z, a0.w, a1.x, a1.y, a1.z, a1.w};
#pragma unroll
            for (int i = 0; i < 8; i++) {
                unsigned long long aa = pack_dup(av[i]);
                fma2(acc2[i][0], aa, b0.x);
                fma2(acc2[i][1], aa, b0.y);
                fma2(acc2[i][2], aa, b1.x);
                fma2(acc2[i][3], aa, b1.y);
            }
        }
        __syncthreads();
    }

    // epilogue: acc2[i][0..1] -> cols tx*4+{0..3}; acc2[i][2..3] -> cols 64+tx*4+{0..3}
    float bc[8];
#pragma unroll
    for (int j = 0; j < 8; j++) {
        int cj = col0 + ((j < 4) ? (tx * 4 + j) : (64 + tx * 4 + j - 4));
        bc[j] = bias ? bias[cj] : 0.0f;
    }
#pragma unroll
    for (int i = 0; i < 8; i++) {
        int ri = row0 + ((i < 4) ? (ty * 4 + i) : (64 + ty * 4 + i - 4));
        if (ri < M) {
            float2 p0 = unpack2(acc2[i][0]);
            float2 p1 = unpack2(acc2[i][1]);
            float2 p2 = unpack2(acc2[i][2]);
            float2 p3 = unpack2(acc2[i][3]);
            float4 o0 = make_float4(p0.x + bc[0], p0.y + bc[1], p1.x + bc[2], p1.y + bc[3]);
            float4 o1 = make_float4(p2.x + bc[4], p2.y + bc[5], p3.x + bc[6], p3.y + bc[7]);
            *(float4*)(C + (size_t)ri * N + col0 + tx * 4)      = o0;
            *(float4*)(C + (size_t)ri * N + col0 + 64 + tx * 4) = o1;
        }
    }
}

// ===================== tf32 tensor-core GEMM-NT (logits projection) =====================
// C[M,N] = A[M,K] * B[N,K]^T + bias[N].  Requires M%128==0, N%128==0, K%16==0, lda=ldb=K.

__global__ __launch_bounds__(256) void gemm_tf32_nt(
    const float* __restrict__ A, const float* __restrict__ Bm,
    const float* __restrict__ bias, float* __restrict__ C,
    int M, int N, int K)
{
    __shared__ float As[2][128][20];
    __shared__ float Bs[2][128][20];

    const int tid  = threadIdx.x;
    const int lane = tid & 31;
    const int wid  = tid >> 5;
    const int wm   = wid >> 1;
    const int wn   = wid & 1;
    const int row0 = blockIdx.y * 128;
    const int col0 = blockIdx.x * 128;

    const int lr  = tid >> 2;
    const int lkq = tid & 3;

    float d[2][8][4];
#pragma unroll
    for (int mt = 0; mt < 2; mt++)
#pragma unroll
        for (int nt = 0; nt < 8; nt++)
#pragma unroll
            for (int q = 0; q < 4; q++) d[mt][nt][q] = 0.0f;

    const int nk = K / 16;

    auto issue = [&](int kt, int p) {
        int k0 = kt * 16;
#pragma unroll
        for (int r = 0; r < 2; r++) {
            int row = lr + r * 64;
            cp16(&As[p][row][lkq * 4], A  + (size_t)(row0 + row) * K + k0 + lkq * 4);
            cp16(&Bs[p][row][lkq * 4], Bm + (size_t)(col0 + row) * K + k0 + lkq * 4);
        }
    };

    issue(0, 0);
    cp_commit();

    int p = 0;
    for (int kt = 0; kt < nk; kt++) {
        if (kt + 1 < nk) {
            issue(kt + 1, p ^ 1);
            cp_commit();
            cp_wait<1>();
        } else {
            cp_wait<0>();
        }
        __syncthreads();

#pragma unroll
        for (int kk = 0; kk < 2; kk++) {
            int k8 = kk * 8;
            uint32_t af[2][4], bf[8][2];
#pragma unroll
            for (int mt = 0; mt < 2; mt++) {
                int mb = wm * 32 + mt * 16;
                af[mt][0] = f2tf(As[p][mb +     (lane >> 2)][k8 +     (lane & 3)]);
                af[mt][1] = f2tf(As[p][mb + 8 + (lane >> 2)][k8 +     (lane & 3)]);
                af[mt][2] = f2tf(As[p][mb +     (lane >> 2)][k8 + 4 + (lane & 3)]);
                af[mt][3] = f2tf(As[p][mb + 8 + (lane >> 2)][k8 + 4 + (lane & 3)]);
            }
#pragma unroll
            for (int nt = 0; nt < 8; nt++) {
                int nb = wn * 64 + nt * 8;
                bf[nt][0] = f2tf(Bs[p][nb + (lane >> 2)][k8 +     (lane & 3)]);
                bf[nt][1] = f2tf(Bs[p][nb + (lane >> 2)][k8 + 4 + (lane & 3)]);
            }
#pragma unroll
            for (int mt = 0; mt < 2; mt++)
#pragma unroll
                for (int nt = 0; nt < 8; nt++)
                    mma_tf32(d[mt][nt], af[mt], bf[nt]);
        }
        __syncthreads();
        p ^= 1;
    }

#pragma unroll
    for (int mt = 0; mt < 2; mt++) {
        int r0 = row0 + wm * 32 + mt * 16 + (lane >> 2);
#pragma unroll
        for (int nt = 0; nt < 8; nt++) {
            int c = col0 + wn * 64 + nt * 8 + (lane & 3) * 2;
            float b0v = bias ? bias[c] : 0.0f;
            float b1v = bias ? bias[c + 1] : 0.0f;
            float2 o0 = make_float2(d[mt][nt][0] + b0v, d[mt][nt][1] + b1v);
            float2 o1 = make_float2(d[mt][nt][2] + b0v, d[mt][nt][3] + b1v);
            *(float2*)(C + (size_t)r0 * N + c)       = o0;
            *(float2*)(C + (size_t)(r0 + 8) * N + c) = o1;
        }
    }
}

// ===================== fused GRU step (v3: FFMA2 + 2j/warp layout) =====================
// grid = DH/8 = 128 CTAs, 256 threads (8 warps).
// Warp w: batch-half bh = w>>2 (lane owns batch b = bh*32 + lane),
//         j-pair jp = w&3 (owns j = jb + jp*2 + {0,1} => 6 Whh gate rows, smem broadcast).
// Each h quad load now feeds 12 FFMA2 (vs 24 scalar FFMA from 2 quads before):
// the h tile is read once per batch-half instead of once per warp -> LDS no longer binding.
// Accumulators are packed f32x2 over adjacent k (exact fp32; horizontal add at the end).

__global__ __launch_bounds__(256) void gru_step(
    const float* __restrict__ gi,    // (B,H3) input-gate preactivations (incl. bih)
    const float* __restrict__ gi2,   // optional second term (decoder ctx), or nullptr
    const float* __restrict__ Whh,   // (H3, DH) row-major
    const float* __restrict__ bhh,   // (H3)
    const float* __restrict__ h_in,  // (B, DH)
    float* __restrict__ h_out,       // (B, DH)
    float* __restrict__ st_out,      // optional: states base + t*DH
    int st_stride)
{
    __shared__ __align__(16) float hs[2][64][68];   // 34816 B
    __shared__ __align__(16) float ws[2][24][68];   // 13056 B

    const int tid  = threadIdx.x;
    const int lane = tid & 31;
    const int w    = tid >> 5;        // 0..7
    const int bh   = w >> 2;          // 0..1
    const int jp   = w & 3;           // 0..3
    const int jb   = blockIdx.x * 8;
    const int b    = bh * 32 + lane;  // this lane's batch row

    unsigned long long acc2[2][3];
#pragma unroll
    for (int jj = 0; jj < 2; jj++)
#pragma unroll
        for (int g = 0; g < 3; g++) acc2[jj][g] = 0ull;

    auto issue = [&](int kt, int p) {
        const int k0 = kt * 64;
        // h tile: 64 rows x 64 k = 1024 float4 -> 4 per thread
#pragma unroll
        for (int r = 0; r < 4; r++) {
            int id  = tid + 256 * r;
            int row = id >> 4;
            int kq  = id & 15;
            cp16(&hs[p][row][kq * 4], h_in + (size_t)row * DH + k0 + kq * 4);
        }
        // Whh rows: 24 x 16 float4 = 384
        {
            int c  = tid >> 4;                 // 0..15
            int kq = tid & 15;
            int jloc = c / 3, g = c - jloc * 3;
            cp16(&ws[p][c][kq * 4],
                 Whh + (size_t)(jb + jloc + g * DH) * DH + k0 + kq * 4);
        }
        if (tid < 128) {
            int id = tid + 256;
            int c  = id >> 4;                  // 16..23
            int kq = id & 15;
            int jloc = c / 3, g = c - jloc * 3;
            cp16(&ws[p][c][kq * 4],
                 Whh + (size_t)(jb + jloc + g * DH) * DH + k0 + kq * 4);
        }
    };

    issue(0, 0);
    cp_commit();

    int p = 0;
    for (int kt = 0; kt < 16; kt++) {
        if (kt < 15) {
            issue(kt + 1, p ^ 1);
            cp_commit();
            cp_wait<1>();
        } else {
            cp_wait<0>();
        }
        __syncthreads();

#pragma unroll
        for (int k4 = 0; k4 < 16; k4++) {
            ulonglong2 av = *(const ulonglong2*)&hs[p][b][k4 * 4];
#pragma unroll
            for (int jj = 0; jj < 2; jj++)
#pragma unroll
                for (int g = 0; g < 3; g++) {
                    ulonglong2 wv =
                        *(const ulonglong2*)&ws[p][(jp * 2 + jj) * 3 + g][k4 * 4];
                    fma2(acc2[jj][g], av.x, wv.x);
                    fma2(acc2[jj][g], av.y, wv.y);
                }
        }
        __syncthreads();
        p ^= 1;
    }

    // fused gate epilogue: lane -> batch b; warp -> j = jb + jp*2 + {0,1}
#pragma unroll
    for (int jj = 0; jj < 2; jj++) {
        int j = jb + jp * 2 + jj;
        float2 pr = unpack2(acc2[jj][0]);
        float2 pz = unpack2(acc2[jj][1]);
        float2 pn = unpack2(acc2[jj][2]);
        float ghr = pr.x + pr.y + bhh[j];
        float ghz = pz.x + pz.y + bhh[j + DH];
        float ghn = pn.x + pn.y + bhh[j + 2 * DH];
        size_t base = (size_t)b * H3 + j;
        float gir = gi[base];
        float giz = gi[base + DH];
        float gin = gi[base + 2 * DH];
        if (gi2) {
            gir += gi2[base];
            giz += gi2[base + DH];
            gin += gi2[base + 2 * DH];
        }
        float rr = 1.0f / (1.0f + expf(-(gir + ghr)));
        float zz = 1.0f / (1.0f + expf(-(giz + ghz)));
        float nn = tanhf(gin + rr * ghn);
        float hold = h_in[(size_t)b * DH + j];
        float hv = (1.0f - zz) * nn + zz * hold;
        h_out[(size_t)b * DH + j] = hv;
        if (st_out) st_out[(size_t)b * st_stride + j] = hv;
    }
}

// ===================== launcher =====================

extern "C" void kernel_launch(void* const* d_in, const int* in_sizes, int n_in,
                              void* d_out, int out_size)
{
    const int*   x        = (const int*)d_in[0];
    const int*   labels   = (const int*)d_in[1];
    const int*   bos      = (const int*)d_in[2];
    const float* enc_emb  = (const float*)d_in[3];
    const float* enc_Wih  = (const float*)d_in[4];
    const float* enc_Whh  = (const float*)d_in[5];
    const float* enc_bih  = (const float*)d_in[6];
    const float* enc_bhh  = (const float*)d_in[7];
    const float* dec_emb  = (const float*)d_in[8];
    const float* dec_Wih  = (const float*)d_in[9];
    const float* dec_Whh  = (const float*)d_in[10];
    const float* dec_bih  = (const float*)d_in[11];
    const float* dec_bhh  = (const float*)d_in[12];
    const float* dec_init = (const float*)d_in[13];
    const float* lin_W    = (const float*)d_in[14];
    const float* lin_b    = (const float*)d_in[15];
    float* out = (float*)d_out;

    float *xe, *gi_enc, *wdec, *gi_dec, *gi_ctx, *hA, *hB, *states;
    cudaGetSymbolAddress((void**)&xe,     g_xe);
    cudaGetSymbolAddress((void**)&gi_enc, g_gi_enc);
    cudaGetSymbolAddress((void**)&wdec,   g_wdec);
    cudaGetSymbolAddress((void**)&gi_dec, g_gi_dec);
    cudaGetSymbolAddress((void**)&gi_ctx, g_gi_ctx);
    cudaGetSymbolAddress((void**)&hA,     g_hA);
    cudaGetSymbolAddress((void**)&hB,     g_hB);
    cudaGetSymbolAddress((void**)&states, g_states);

    // ---- encoder ----
    gather_enc<<<TE * BB, 128>>>(x, enc_emb, xe);
    sgemm_nt<<<dim3(H3 / 128, (TE * BB) / 128), 256>>>(
        xe, enc_Wih, enc_bih, gi_enc, TE * BB, H3, DE, DE, DE);
    set_h<<<64, 1024>>>(hA, nullptr);
    for (int t = 0; t < TE; t++) {
        float* hin  = (t & 1) ? hB : hA;
        float* hout = (t & 1) ? hA : hB;
        gru_step<<<DH / 8, 256>>>(gi_enc + (size_t)t * BB * H3, nullptr,
                                  enc_Whh, enc_bhh, hin, hout, nullptr, 0);
    }
    // encoder final hidden state now in hA (TE even)

    // ---- decoder precompute ----
    gather_dec<<<TD * BB, 128>>>(labels, bos, dec_emb, wdec);
    sgemm_nt<<<dim3(H3 / 128, (TD * BB) / 128), 256>>>(
        wdec, dec_Wih, dec_bih, gi_dec, TD * BB, H3, DE, DE, DIN);
    sgemm_nt<<<dim3(H3 / 128, 1), 256>>>(
        hA, dec_Wih + DE, nullptr, gi_ctx, BB, H3, DH, DH, DIN);
    set_h<<<64, 1024>>>(hA, dec_init);

    // ---- decoder recurrence ----
    for (int t = 0; t < TD; t++) {
        float* hin  = (t & 1) ? hB : hA;
        float* hout = (t & 1) ? hA : hB;
        gru_step<<<DH / 8, 256>>>(gi_dec + (size_t)t * BB * H3, gi_ctx,
                                  dec_Whh, dec_bhh, hin, hout,
                                  states + (size_t)t * DH, TD * DH);
    }

    // ---- output projection (tf32 tensor cores): logits = states * lin_W^T + lin_b ----
    gemm_tf32_nt<<<dim3(VV / 128, (TD * BB) / 128), 256>>>(
        states, lin_W, lin_b, out, TD * BB, VV, DH);
}